// round 3
// baseline (speedup 1.0000x reference)
#include <cuda_runtime.h>
#include <cstdint>

// ---------------------------------------------------------------------------
// NeuralMJDFinancial: exact reproduction of the JAX reference on GB300.
// L=96, D=64, H=24, WID=256, K=1024, M=20. Output (K,H,D) f32 = 1,572,864.
//
// RNG: Threefry-2x32 (20 rounds), jax_threefry_partitionable semantics:
//   random_bits(key, shape)[e] = x0 ^ x1 of threefry(key, (hi=0, lo=e))
//   split(key, n)[i]           = threefry(key, (0, i))  (full 2x32 output)
// Normal: u = max(lo, f*2 + lo), lo = nextafter(-1,0);  sqrt(2)*erfinv_XLA(u)
// Poisson (Knuth, lam<10 always): n = (min t>=1 : sum log u_t <= -lam) - 1,
//   u_t from subkey chain rng,sub = split(rng).
// ---------------------------------------------------------------------------

#define DD 64
#define HH 24
#define LL 96
#define WID 256
#define MM 20
#define NSUB 64

__device__ float g_mu[HH * DD];
__device__ float g_base[HH * DD];   // prev_mean + M*alpha
__device__ float g_ssd[HH * DD];    // sigma * sqrt(dt)
__device__ float g_lam[HH * DD];    // lambda_/M   (poisson rate)
__device__ float g_nu[HH * DD];
__device__ float g_gm[HH * DD];
__device__ float g_a20[HH * DD];    // M*alpha
__device__ uint2 g_kdiff;
__device__ uint2 g_kjmag;
__device__ uint2 g_sub[NSUB + 2];

// ---------------- Threefry-2x32, 20 rounds ----------------
#define TFR(r) { x0 += x1; x1 = (x1 << (r)) | (x1 >> (32 - (r))); x1 ^= x0; }

__device__ __forceinline__ uint2 tf2x32(unsigned k0, unsigned k1,
                                        unsigned x0, unsigned x1) {
    unsigned k2 = k0 ^ k1 ^ 0x1BD11BDAu;
    x0 += k0; x1 += k1;
    TFR(13) TFR(15) TFR(26) TFR(6)
    x0 += k1; x1 += k2 + 1u;
    TFR(17) TFR(29) TFR(16) TFR(24)
    x0 += k2; x1 += k0 + 2u;
    TFR(13) TFR(15) TFR(26) TFR(6)
    x0 += k0; x1 += k1 + 3u;
    TFR(17) TFR(29) TFR(16) TFR(24)
    x0 += k1; x1 += k2 + 4u;
    TFR(13) TFR(15) TFR(26) TFR(6)
    x0 += k2; x1 += k0 + 5u;
    return make_uint2(x0, x1);
}

// partitionable random_bits: single element e -> x0^x1 of threefry(key,(0,e))
__device__ __forceinline__ unsigned tf_bits(uint2 key, unsigned e) {
    uint2 r = tf2x32(key.x, key.y, 0u, e);
    return r.x ^ r.y;
}

// uniform [0,1): bitcast((bits>>9)|0x3f800000) - 1
__device__ __forceinline__ float u01(unsigned b) {
    return __uint_as_float((b >> 9) | 0x3f800000u) - 1.0f;
}

// XLA f32 erfinv (Giles), exactly as in xla/client/lib/math.cc
__device__ __forceinline__ float erfinv_xla(float x) {
    float w = -log1pf(-x * x);
    float p;
    if (w < 5.0f) {
        w -= 2.5f;
        p = 2.81022636e-08f;
        p = fmaf(p, w, 3.43273939e-07f);
        p = fmaf(p, w, -3.5233877e-06f);
        p = fmaf(p, w, -4.39150654e-06f);
        p = fmaf(p, w, 0.00021858087f);
        p = fmaf(p, w, -0.00125372503f);
        p = fmaf(p, w, -0.00417768164f);
        p = fmaf(p, w, 0.246640727f);
        p = fmaf(p, w, 1.50140941f);
    } else {
        w = sqrtf(w) - 3.0f;
        p = -0.000200214257f;
        p = fmaf(p, w, 0.000100950558f);
        p = fmaf(p, w, 0.00134934322f);
        p = fmaf(p, w, -0.00367342844f);
        p = fmaf(p, w, 0.00573950773f);
        p = fmaf(p, w, -0.0076224613f);
        p = fmaf(p, w, 0.00943887047f);
        p = fmaf(p, w, 1.00167406f);
        p = fmaf(p, w, 2.83297682f);
    }
    return p * x;
}

// jax.random.normal(f32): sqrt(2)*erfinv(uniform(lo, 1)), lo = nextafter(-1,0).
// maxval-minval rounds exactly to 2.0f; f*2 is exact.
__device__ __forceinline__ float jnorm(unsigned bits) {
    const float LO = -0.99999994f;  // 0xBF7FFFFF
    float f = u01(bits);
    float u = fmaxf(LO, f * 2.0f + LO);
    return 1.41421356237309515f * erfinv_xla(u);
}

__device__ __forceinline__ float jsigmoid(float x) {
    return 1.0f / (1.0f + expf(-x));
}

// ---------------- Kernel A: per-channel encoder MLP ----------------
__global__ void encoder_kernel(const float* __restrict__ x,
                               const float* __restrict__ W0, const float* __restrict__ b0,
                               const float* __restrict__ W1, const float* __restrict__ b1,
                               const float* __restrict__ W2, const float* __restrict__ b2,
                               const float* __restrict__ W3, const float* __restrict__ b3) {
    int d = blockIdx.x;     // 0..63
    int w = threadIdx.x;    // 0..255
    __shared__ float sa[WID];
    __shared__ float sb[WID];

    if (w < LL) sa[w] = x[w * DD + d];  // xt[d, :]
    __syncthreads();

    float acc = b0[w];
    #pragma unroll 8
    for (int l = 0; l < LL; l++) acc = fmaf(W0[w * LL + l], sa[l], acc);
    sb[w] = fmaxf(acc, 0.0f);
    __syncthreads();

    acc = b1[w];
    #pragma unroll 8
    for (int j = 0; j < WID; j++) acc = fmaf(W1[w * WID + j], sb[j], acc);
    sa[w] = fmaxf(acc, 0.0f);
    __syncthreads();

    acc = b2[w];
    #pragma unroll 8
    for (int j = 0; j < WID; j++) acc = fmaf(W2[w * WID + j], sa[j], acc);
    sb[w] = fmaxf(acc, 0.0f);
    __syncthreads();

    float raw = 0.0f;
    if (w < HH * 5) {
        acc = b3[w];
        #pragma unroll 8
        for (int j = 0; j < WID; j++) acc = fmaf(W3[w * WID + j], sb[j], acc);
        raw = acc;
    }
    __syncthreads();
    sa[w] = raw;
    __syncthreads();

    if (w < HH) {
        int h = w;
        float mu  = sa[h * 5 + 0];
        float sg  = jsigmoid(sa[h * 5 + 1]);
        float ll  = sa[h * 5 + 2];
        float nu  = tanhf(sa[h * 5 + 3]) * 0.5f;
        float gm  = jsigmoid(sa[h * 5 + 4]);
        float lam = expf(fminf(ll, 0.0f));
        float km  = expf(nu + 0.5f * gm * gm) - 1.0f;
        float alpha = (mu - lam * km - 0.5f * sg * sg) * 0.05f;  // * dt
        int idx = h * DD + d;
        g_mu[idx]  = mu;
        g_ssd[idx] = sg * sqrtf(0.05f);
        g_lam[idx] = lam / 20.0f;
        g_nu[idx]  = nu;
        g_gm[idx]  = gm;
        g_a20[idx] = 20.0f * alpha;
    }
}

// ---------------- Kernel B: cumsum base + RNG key chain ----------------
__global__ void finalize_kernel(const float* __restrict__ x,
                                const int* __restrict__ seed_ptr) {
    int tid = blockIdx.x * blockDim.x + threadIdx.x;  // 0..1535 = h*64+d
    if (tid < HH * DD) {
        int d = tid & (DD - 1);
        int h = tid >> 6;
        float c = 0.0f;
        for (int i = 0; i < h; i++) c += g_mu[i * DD + d];  // ascending cumsum
        float s0 = x[(LL - 1) * DD + d];
        float pm = (h == 0) ? s0 : (s0 + c);
        g_base[tid] = pm + g_a20[tid];
    }
    if (tid == 0) {
        unsigned seed = (unsigned)(*seed_ptr);
        uint2 key = make_uint2(0u, seed);
        // split(key, 3) partitionable: ks[i] = threefry(key, (0, i))
        g_kdiff = tf2x32(key.x, key.y, 0u, 0u);
        uint2 kp = tf2x32(key.x, key.y, 0u, 1u);
        g_kjmag = tf2x32(key.x, key.y, 0u, 2u);
        // poisson subkey chain: rng, sub = split(rng)
        uint2 rng = kp;
        for (int t = 1; t <= NSUB; t++) {
            uint2 nr = tf2x32(rng.x, rng.y, 0u, 0u);
            g_sub[t] = tf2x32(rng.x, rng.y, 0u, 1u);
            rng = nr;
        }
    }
}

// ---------------- Kernel C: main Monte-Carlo accumulation ----------------
__global__ void __launch_bounds__(256) mjd_main(float* __restrict__ out) {
    int tid = blockIdx.x * 256 + threadIdx.x;      // = (k*H + h)*D + d
    int d  = tid & (DD - 1);
    int kh = tid >> 6;                             // k*H + h
    int hd = (kh % HH) * DD + d;

    float mlam = -g_lam[hd];
    float nu = g_nu[hd], gm = g_gm[hd], ssd = g_ssd[hd], base = g_base[hd];
    uint2 kdiff = g_kdiff, kjmag = g_kjmag;
    uint2 sub1 = g_sub[1];

    unsigned ebase = (unsigned)kh * (MM * DD) + (unsigned)d;

    float accd = 0.0f, jn = 0.0f, wj = 0.0f;

    #pragma unroll 1
    for (int m = 0; m < MM; m++) {
        unsigned e = ebase + (unsigned)(m * DD);

        // diffusion normal (always needed)
        accd += jnorm(tf_bits(kdiff, e));

        // Knuth poisson: first draw always happens (0 > -lam since lam > 0)
        float lp = logf(u01(tf_bits(sub1, e)));
        int n = 1;
        #pragma unroll 1
        for (int t = 2; t <= NSUB && lp > mlam; t++) {
            n++;
            lp += logf(u01(tf_bits(g_sub[t], e)));
        }
        float nj = (float)(n - 1);
        jn += nj;

        // jump-magnitude normal: only its sqrt(nj)-weighted value matters
        if (__any_sync(0xffffffffu, nj > 0.0f)) {
            float ej = jnorm(tf_bits(kjmag, e));
            wj += sqrtf(nj) * ej;
        }
    }

    float diff = ssd * accd;
    float jump = nu * jn + gm * wj;
    out[tid] = (base + diff) + jump;
}

// ---------------- launch ----------------
extern "C" void kernel_launch(void* const* d_in, const int* in_sizes, int n_in,
                              void* d_out, int out_size) {
    const float* x  = (const float*)d_in[0];
    const float* W0 = (const float*)d_in[1];
    const float* b0 = (const float*)d_in[2];
    const float* W1 = (const float*)d_in[3];
    const float* b1 = (const float*)d_in[4];
    const float* W2 = (const float*)d_in[5];
    const float* b2 = (const float*)d_in[6];
    const float* W3 = (const float*)d_in[7];
    const float* b3 = (const float*)d_in[8];
    const int* seed = (const int*)d_in[11];
    float* out = (float*)d_out;

    encoder_kernel<<<DD, WID>>>(x, W0, b0, W1, b1, W2, b2, W3, b3);
    finalize_kernel<<<(HH * DD + 255) / 256, 256>>>(x, seed);
    mjd_main<<<out_size / 256, 256>>>(out);
}

// round 4
// speedup vs baseline: 1.7552x; 1.7552x over previous
#include <cuda_runtime.h>
#include <cstdint>

// ---------------------------------------------------------------------------
// NeuralMJDFinancial: exact JAX (threefry-partitionable) reproduction.
// L=96, D=64, H=24, WID=256, K=1024, M=20. Output (K,H,D) f32.
//
// R4 changes vs R3 (534.7us, rel_err 6.8e-8):
//  * encoder: warp-split-K, coalesced LDG.128 + shfl reduction (99.5us -> ~8us)
//  * mjd_main: defer rare Poisson continuations + jump normals into a
//    per-warp shared queue; process packed 32-wide (kills warp-any waste).
//    Boundary decisions (logf(u) > -lam) are computed identically to R3.
// ---------------------------------------------------------------------------

#define DD 64
#define HH 24
#define LL 96
#define WID 256
#define MM 20
#define NSUB 64
#define QMAX 128

__device__ float g_mu[HH * DD];
__device__ float g_base[HH * DD];   // prev_mean + M*alpha
__device__ float g_ssd[HH * DD];    // sigma * sqrt(dt)
__device__ float g_lam[HH * DD];    // lambda_/M   (poisson rate)
__device__ float g_nu[HH * DD];
__device__ float g_gm[HH * DD];
__device__ float g_a20[HH * DD];    // M*alpha
__device__ uint2 g_kdiff;
__device__ uint2 g_kjmag;
__device__ uint2 g_sub[NSUB + 2];

// ---------------- Threefry-2x32, 20 rounds ----------------
#define TFR(r) { x0 += x1; x1 = (x1 << (r)) | (x1 >> (32 - (r))); x1 ^= x0; }

__device__ __forceinline__ uint2 tf2x32(unsigned k0, unsigned k1,
                                        unsigned x0, unsigned x1) {
    unsigned k2 = k0 ^ k1 ^ 0x1BD11BDAu;
    x0 += k0; x1 += k1;
    TFR(13) TFR(15) TFR(26) TFR(6)
    x0 += k1; x1 += k2 + 1u;
    TFR(17) TFR(29) TFR(16) TFR(24)
    x0 += k2; x1 += k0 + 2u;
    TFR(13) TFR(15) TFR(26) TFR(6)
    x0 += k0; x1 += k1 + 3u;
    TFR(17) TFR(29) TFR(16) TFR(24)
    x0 += k1; x1 += k2 + 4u;
    TFR(13) TFR(15) TFR(26) TFR(6)
    x0 += k2; x1 += k0 + 5u;
    return make_uint2(x0, x1);
}

__device__ __forceinline__ unsigned tf_bits(uint2 key, unsigned e) {
    uint2 r = tf2x32(key.x, key.y, 0u, e);
    return r.x ^ r.y;
}

__device__ __forceinline__ float u01(unsigned b) {
    return __uint_as_float((b >> 9) | 0x3f800000u) - 1.0f;
}

// XLA f32 erfinv (Giles)
__device__ __forceinline__ float erfinv_xla(float x) {
    float w = -log1pf(-x * x);
    float p;
    if (w < 5.0f) {
        w -= 2.5f;
        p = 2.81022636e-08f;
        p = fmaf(p, w, 3.43273939e-07f);
        p = fmaf(p, w, -3.5233877e-06f);
        p = fmaf(p, w, -4.39150654e-06f);
        p = fmaf(p, w, 0.00021858087f);
        p = fmaf(p, w, -0.00125372503f);
        p = fmaf(p, w, -0.00417768164f);
        p = fmaf(p, w, 0.246640727f);
        p = fmaf(p, w, 1.50140941f);
    } else {
        w = sqrtf(w) - 3.0f;
        p = -0.000200214257f;
        p = fmaf(p, w, 0.000100950558f);
        p = fmaf(p, w, 0.00134934322f);
        p = fmaf(p, w, -0.00367342844f);
        p = fmaf(p, w, 0.00573950773f);
        p = fmaf(p, w, -0.0076224613f);
        p = fmaf(p, w, 0.00943887047f);
        p = fmaf(p, w, 1.00167406f);
        p = fmaf(p, w, 2.83297682f);
    }
    return p * x;
}

__device__ __forceinline__ float jnorm(unsigned bits) {
    const float LO = -0.99999994f;  // 0xBF7FFFFF
    float f = u01(bits);
    float u = fmaxf(LO, f * 2.0f + LO);
    return 1.41421356237309515f * erfinv_xla(u);
}

__device__ __forceinline__ float jsigmoid(float x) {
    return 1.0f / (1.0f + expf(-x));
}

// ---------------- Kernel A: per-channel encoder MLP (warp-split-K) --------
__global__ void __launch_bounds__(WID) encoder_kernel(
        const float* __restrict__ x,
        const float* __restrict__ W0, const float* __restrict__ b0,
        const float* __restrict__ W1, const float* __restrict__ b1,
        const float* __restrict__ W2, const float* __restrict__ b2,
        const float* __restrict__ W3, const float* __restrict__ b3) {
    int d = blockIdx.x;       // 0..63
    int tid = threadIdx.x;    // 0..255
    int wp = tid >> 5, lane = tid & 31;
    __shared__ __align__(16) float sa[WID];
    __shared__ __align__(16) float sb[WID];

    if (tid < LL) sa[tid] = x[tid * DD + d];   // xt[d, :]
    __syncthreads();

    // layer 0: 96 -> 256 (lanes split K: 3 scalar chunks)
    #pragma unroll 4
    for (int i = 0; i < 32; i++) {
        int w = wp * 32 + i;
        const float* Wr = W0 + w * LL;
        float v = Wr[lane] * sa[lane];
        v = fmaf(Wr[lane + 32], sa[lane + 32], v);
        v = fmaf(Wr[lane + 64], sa[lane + 64], v);
        #pragma unroll
        for (int o = 16; o; o >>= 1) v += __shfl_xor_sync(0xffffffffu, v, o);
        if (lane == 0) sb[w] = fmaxf(v + b0[w], 0.0f);
    }
    __syncthreads();

    // layer 1: 256 -> 256 (float4 split-K)
    {
        const float4* W4 = (const float4*)W1;
        const float4* in4 = (const float4*)sb;
        float4 x0 = in4[lane], x1 = in4[lane + 32];
        #pragma unroll 4
        for (int i = 0; i < 32; i++) {
            int w = wp * 32 + i;
            float4 a0 = W4[w * 64 + lane];
            float4 a1 = W4[w * 64 + lane + 32];
            float v = a0.x * x0.x;
            v = fmaf(a0.y, x0.y, v); v = fmaf(a0.z, x0.z, v); v = fmaf(a0.w, x0.w, v);
            v = fmaf(a1.x, x1.x, v); v = fmaf(a1.y, x1.y, v);
            v = fmaf(a1.z, x1.z, v); v = fmaf(a1.w, x1.w, v);
            #pragma unroll
            for (int o = 16; o; o >>= 1) v += __shfl_xor_sync(0xffffffffu, v, o);
            if (lane == 0) sa[w] = fmaxf(v + b1[w], 0.0f);
        }
    }
    __syncthreads();

    // layer 2: 256 -> 256
    {
        const float4* W4 = (const float4*)W2;
        const float4* in4 = (const float4*)sa;
        float4 x0 = in4[lane], x1 = in4[lane + 32];
        #pragma unroll 4
        for (int i = 0; i < 32; i++) {
            int w = wp * 32 + i;
            float4 a0 = W4[w * 64 + lane];
            float4 a1 = W4[w * 64 + lane + 32];
            float v = a0.x * x0.x;
            v = fmaf(a0.y, x0.y, v); v = fmaf(a0.z, x0.z, v); v = fmaf(a0.w, x0.w, v);
            v = fmaf(a1.x, x1.x, v); v = fmaf(a1.y, x1.y, v);
            v = fmaf(a1.z, x1.z, v); v = fmaf(a1.w, x1.w, v);
            #pragma unroll
            for (int o = 16; o; o >>= 1) v += __shfl_xor_sync(0xffffffffu, v, o);
            if (lane == 0) sb[w] = fmaxf(v + b2[w], 0.0f);
        }
    }
    __syncthreads();

    // layer 3: 256 -> 120 (warps 0..3)
    if (wp < 4) {
        const float4* W4 = (const float4*)W3;
        const float4* in4 = (const float4*)sb;
        float4 x0 = in4[lane], x1 = in4[lane + 32];
        #pragma unroll 4
        for (int i = 0; i < 32; i++) {
            int w = wp * 32 + i;
            if (w < HH * 5) {
                float4 a0 = W4[w * 64 + lane];
                float4 a1 = W4[w * 64 + lane + 32];
                float v = a0.x * x0.x;
                v = fmaf(a0.y, x0.y, v); v = fmaf(a0.z, x0.z, v); v = fmaf(a0.w, x0.w, v);
                v = fmaf(a1.x, x1.x, v); v = fmaf(a1.y, x1.y, v);
                v = fmaf(a1.z, x1.z, v); v = fmaf(a1.w, x1.w, v);
                #pragma unroll
                for (int o = 16; o; o >>= 1) v += __shfl_xor_sync(0xffffffffu, v, o);
                if (lane == 0) sa[w] = v + b3[w];
            }
        }
    }
    __syncthreads();

    if (tid < HH) {
        int h = tid;
        float mu  = sa[h * 5 + 0];
        float sg  = jsigmoid(sa[h * 5 + 1]);
        float ll  = sa[h * 5 + 2];
        float nu  = tanhf(sa[h * 5 + 3]) * 0.5f;
        float gm  = jsigmoid(sa[h * 5 + 4]);
        float lam = expf(fminf(ll, 0.0f));
        float km  = expf(nu + 0.5f * gm * gm) - 1.0f;
        float alpha = (mu - lam * km - 0.5f * sg * sg) * 0.05f;
        int idx = h * DD + d;
        g_mu[idx]  = mu;
        g_ssd[idx] = sg * sqrtf(0.05f);
        g_lam[idx] = lam / 20.0f;
        g_nu[idx]  = nu;
        g_gm[idx]  = gm;
        g_a20[idx] = 20.0f * alpha;
    }
}

// ---------------- Kernel B: cumsum base + RNG key chain ----------------
__global__ void finalize_kernel(const float* __restrict__ x,
                                const int* __restrict__ seed_ptr) {
    int tid = blockIdx.x * blockDim.x + threadIdx.x;
    if (tid < HH * DD) {
        int d = tid & (DD - 1);
        int h = tid >> 6;
        float c = 0.0f;
        for (int i = 0; i < h; i++) c += g_mu[i * DD + d];
        float s0 = x[(LL - 1) * DD + d];
        float pm = (h == 0) ? s0 : (s0 + c);
        g_base[tid] = pm + g_a20[tid];
    }
    if (tid == 0) {
        unsigned seed = (unsigned)(*seed_ptr);
        uint2 key = make_uint2(0u, seed);
        g_kdiff = tf2x32(key.x, key.y, 0u, 0u);
        uint2 kp = tf2x32(key.x, key.y, 0u, 1u);
        g_kjmag = tf2x32(key.x, key.y, 0u, 2u);
        uint2 rng = kp;
        for (int t = 1; t <= NSUB; t++) {
            uint2 nr = tf2x32(rng.x, rng.y, 0u, 0u);
            g_sub[t] = tf2x32(rng.x, rng.y, 0u, 1u);
            rng = nr;
        }
    }
}

// ---------------- Kernel C: main Monte-Carlo (deferred rare work) ---------
__global__ void __launch_bounds__(256) mjd_main(float* __restrict__ out) {
    __shared__ unsigned sqe[8][QMAX];   // packed: e | (origin_lane << 25)
    __shared__ float    sqlp[8][QMAX];  // log u1 at queue time
    __shared__ float    sjn[8][32];     // sum n_j returned to origin
    __shared__ float    swj[8][32];     // sum sqrt(n_j)*eps_j returned

    int tid = blockIdx.x * 256 + threadIdx.x;   // = (k*H + h)*D + d
    int lane = threadIdx.x & 31, wp = threadIdx.x >> 5;
    sjn[wp][lane] = 0.0f;
    swj[wp][lane] = 0.0f;

    int d  = tid & (DD - 1);
    int kh = tid >> 6;
    int hd = (kh % HH) * DD + d;

    float mlam = -g_lam[hd];
    float nu = g_nu[hd], gm = g_gm[hd], ssd = g_ssd[hd], base = g_base[hd];
    uint2 kdiff = g_kdiff, kjmag = g_kjmag, sub1 = g_sub[1];

    unsigned e = (unsigned)kh * (MM * DD) + (unsigned)d;
    const unsigned lmask = (1u << lane) - 1u;

    float accd = 0.0f, jn_loc = 0.0f, wj_loc = 0.0f;
    int cnt = 0;

    // -------- phase 1: unconditional work, queue rare continuations --------
    #pragma unroll 2
    for (int m = 0; m < MM; m++) {
        // diffusion normal (always)
        accd += jnorm(tf_bits(kdiff, e));

        // poisson first draw (always) — decision identical to reference
        float lp = logf(u01(tf_bits(sub1, e)));
        bool need = lp > mlam;                 // nj >= 1
        unsigned bm = __ballot_sync(0xffffffffu, need);
        if (bm) {
            int add = __popc(bm);
            if (cnt + add <= QMAX) {
                if (need) {
                    int pos = cnt + __popc(bm & lmask);
                    sqe[wp][pos]  = e | ((unsigned)lane << 25);
                    sqlp[wp][pos] = lp;
                }
                cnt += add;
            } else if (need) {
                // overflow fallback: resolve inline (same math)
                float njf = 0.0f;
                int t = 2;
                do {
                    lp += logf(u01(tf_bits(g_sub[t], e)));
                    t++; njf += 1.0f;
                } while (lp > mlam && t <= NSUB);
                jn_loc += njf;
                wj_loc += sqrtf(njf) * jnorm(tf_bits(kjmag, e));
            }
        }
        e += DD;
    }

    __syncwarp();

    // -------- phase 2: packed processing of queued items --------
    for (int bse = 0; bse < cnt; bse += 32) {
        int idx = bse + lane;
        bool act = idx < cnt;
        unsigned pk = act ? sqe[wp][idx] : 0u;
        float lp    = act ? sqlp[wp][idx] : 0.0f;
        unsigned ee = pk & 0x01FFFFFFu;
        int org     = (int)(pk >> 25);
        float mlam_o = __shfl_sync(0xffffffffu, mlam, org);
        if (act) {
            float njf = 0.0f;
            int t = 2;
            do {
                lp += logf(u01(tf_bits(g_sub[t], ee)));
                t++; njf += 1.0f;
            } while (lp > mlam_o && t <= NSUB);
            float ej = jnorm(tf_bits(kjmag, ee));
            atomicAdd(&sjn[wp][org], njf);
            atomicAdd(&swj[wp][org], sqrtf(njf) * ej);
        }
    }

    __syncwarp();

    float jn = jn_loc + sjn[wp][lane];
    float wj = wj_loc + swj[wp][lane];
    out[tid] = (base + ssd * accd) + (nu * jn + gm * wj);
}

// ---------------- launch ----------------
extern "C" void kernel_launch(void* const* d_in, const int* in_sizes, int n_in,
                              void* d_out, int out_size) {
    const float* x  = (const float*)d_in[0];
    const float* W0 = (const float*)d_in[1];
    const float* b0 = (const float*)d_in[2];
    const float* W1 = (const float*)d_in[3];
    const float* b1 = (const float*)d_in[4];
    const float* W2 = (const float*)d_in[5];
    const float* b2 = (const float*)d_in[6];
    const float* W3 = (const float*)d_in[7];
    const float* b3 = (const float*)d_in[8];
    const int* seed = (const int*)d_in[11];
    float* out = (float*)d_out;

    encoder_kernel<<<DD, WID>>>(x, W0, b0, W1, b1, W2, b2, W3, b3);
    finalize_kernel<<<(HH * DD + 255) / 256, 256>>>(x, seed);
    mjd_main<<<out_size / 256, 256>>>(out);
}

// round 5
// speedup vs baseline: 2.0681x; 1.1782x over previous
#include <cuda_runtime.h>
#include <cstdint>

// ---------------------------------------------------------------------------
// NeuralMJDFinancial: exact JAX (threefry-partitionable) reproduction.
// L=96, D=64, H=24, WID=256, K=1024, M=20. Output (K,H,D) f32.
//
// R5 vs R4 (304.6us, rel_err 2.4e-7):
//  * encoder -> 4 batched layer kernels (256 blocks each, all channels at once)
//  * mjd_main phase 1: Poisson first-draw decision via precomputed float
//    threshold (bit-identical decisions to logf compare); fast erfinv log
//    (-__logf(fma(x,-x,1))) for the normals. Precise logf kept for all
//    count-determining sums in phase 2.
// ---------------------------------------------------------------------------

#define DD 64
#define HH 24
#define LL 96
#define WID 256
#define MM 20
#define NSUB 64
#define QMAX 128

__device__ float g_bufA[WID * DD];
__device__ float g_bufB[WID * DD];
__device__ float g_raw[HH * 5 * DD];
__device__ float g_mu[HH * DD];
__device__ float g_base[HH * DD];   // prev_mean + M*alpha
__device__ float g_ssd[HH * DD];    // sigma * sqrt(dt)
__device__ float g_mlam[HH * DD];   // -lambda_/M
__device__ float g_cut[HH * DD];    // decision threshold on u
__device__ float g_nu[HH * DD];
__device__ float g_gm[HH * DD];
__device__ float g_a20[HH * DD];    // M*alpha
__device__ uint2 g_kdiff;
__device__ uint2 g_kjmag;
__device__ uint2 g_sub[NSUB + 2];

// ---------------- Threefry-2x32, 20 rounds ----------------
#define TFR(r) { x0 += x1; x1 = __funnelshift_l(x1, x1, (r)); x1 ^= x0; }

__device__ __forceinline__ uint2 tf2x32(unsigned k0, unsigned k1,
                                        unsigned x0, unsigned x1) {
    unsigned k2 = k0 ^ k1 ^ 0x1BD11BDAu;
    x0 += k0; x1 += k1;
    TFR(13) TFR(15) TFR(26) TFR(6)
    x0 += k1; x1 += k2 + 1u;
    TFR(17) TFR(29) TFR(16) TFR(24)
    x0 += k2; x1 += k0 + 2u;
    TFR(13) TFR(15) TFR(26) TFR(6)
    x0 += k0; x1 += k1 + 3u;
    TFR(17) TFR(29) TFR(16) TFR(24)
    x0 += k1; x1 += k2 + 4u;
    TFR(13) TFR(15) TFR(26) TFR(6)
    x0 += k2; x1 += k0 + 5u;
    return make_uint2(x0, x1);
}

__device__ __forceinline__ unsigned tf_bits(uint2 key, unsigned e) {
    uint2 r = tf2x32(key.x, key.y, 0u, e);
    return r.x ^ r.y;
}

__device__ __forceinline__ float u01(unsigned b) {
    return __uint_as_float((b >> 9) | 0x3f800000u) - 1.0f;
}

// XLA Giles erfinv polys (shared by fast/precise variants)
__device__ __forceinline__ float erfinv_poly(float w, float x) {
    float p;
    if (w < 5.0f) {
        w -= 2.5f;
        p = 2.81022636e-08f;
        p = fmaf(p, w, 3.43273939e-07f);
        p = fmaf(p, w, -3.5233877e-06f);
        p = fmaf(p, w, -4.39150654e-06f);
        p = fmaf(p, w, 0.00021858087f);
        p = fmaf(p, w, -0.00125372503f);
        p = fmaf(p, w, -0.00417768164f);
        p = fmaf(p, w, 0.246640727f);
        p = fmaf(p, w, 1.50140941f);
    } else {
        w = sqrtf(w) - 3.0f;
        p = -0.000200214257f;
        p = fmaf(p, w, 0.000100950558f);
        p = fmaf(p, w, 0.00134934322f);
        p = fmaf(p, w, -0.00367342844f);
        p = fmaf(p, w, 0.00573950773f);
        p = fmaf(p, w, -0.0076224613f);
        p = fmaf(p, w, 0.00943887047f);
        p = fmaf(p, w, 1.00167406f);
        p = fmaf(p, w, 2.83297682f);
    }
    return 1.41421356237309515f * p * x;
}

// fast: w = -__logf(1 - x^2) with exact 1-x^2 via FMA (~1e-6 abs error,
// no effect on any discrete decision)
__device__ __forceinline__ float jnorm_fast(unsigned bits) {
    const float LO = -0.99999994f;  // 0xBF7FFFFF
    float f = u01(bits);
    float x = fmaxf(LO, fmaf(f, 2.0f, LO));
    float w = -__logf(fmaf(x, -x, 1.0f));
    return erfinv_poly(w, x);
}

__device__ __forceinline__ float jsigmoid(float x) {
    return 1.0f / (1.0f + expf(-x));
}

// ---------------- Encoder: one block per output row, all 64 channels ------
// out[w*64+d] = act(sum_k W[w*K+k] * in[k*64+d] + b[w])
template<int K, bool RELU>
__global__ void __launch_bounds__(256) enc_layer(
        const float* __restrict__ W, const float* __restrict__ b,
        const float* __restrict__ in, float* __restrict__ outp) {
    const int KS = K / 4;
    int tid = threadIdx.x;
    int d = tid & 63, ks = tid >> 6;
    int w = blockIdx.x;
    const float* Wr  = W + w * K + ks * KS;
    const float* inp = in + ks * KS * 64 + d;
    float acc = 0.0f;
    #pragma unroll 8
    for (int j = 0; j < KS; j++)
        acc = fmaf(Wr[j], inp[j * 64], acc);
    __shared__ float sp[256];
    sp[tid] = acc;
    __syncthreads();
    if (tid < 64) {
        float v = ((sp[tid] + sp[tid + 64]) + sp[tid + 128]) + sp[tid + 192];
        v += b[w];
        outp[w * 64 + tid] = RELU ? fmaxf(v, 0.0f) : v;
    }
}

// ---------------- finalize: params, cut thresholds, cumsum base, keys -----
__global__ void __launch_bounds__(512) finalize_kernel(
        const float* __restrict__ x, const int* __restrict__ seed_ptr) {
    int tid = threadIdx.x;
    for (int i = tid; i < HH * DD; i += 512) {
        int d = i & 63, h = i >> 6;
        float mu  = g_raw[(h * 5 + 0) * 64 + d];
        float sg  = jsigmoid(g_raw[(h * 5 + 1) * 64 + d]);
        float ll  = g_raw[(h * 5 + 2) * 64 + d];
        float nuv = tanhf(g_raw[(h * 5 + 3) * 64 + d]) * 0.5f;
        float gmv = jsigmoid(g_raw[(h * 5 + 4) * 64 + d]);
        float lam = expf(fminf(ll, 0.0f));
        float km  = expf(nuv + 0.5f * gmv * gmv) - 1.0f;
        float alpha = (mu - lam * km - 0.5f * sg * sg) * 0.05f;
        g_mu[i]  = mu;
        g_ssd[i] = sg * sqrtf(0.05f);
        g_nu[i]  = nuv;
        g_gm[i]  = gmv;
        g_a20[i] = 20.0f * alpha;
        float mlam = -(lam / 20.0f);
        g_mlam[i] = mlam;
        // exact cut: largest grid u with logf(u) <= mlam. u-grid = j*2^-23.
        // decisions then reproduce (logf(u) > mlam) bit-identically.
        float t = expf(mlam);
        int j0 = (int)(t * 8388608.0f);
        int lo = j0 - 8 < 0 ? 0 : j0 - 8;
        int hi = j0 + 8 > 8388607 ? 8388607 : j0 + 8;
        float cut = 0.0f;
        for (int j = lo; j <= hi; j++) {
            float u = __uint_as_float(0x3f800000u | (unsigned)j) - 1.0f;
            if (logf(u) <= mlam) cut = u;   // logf monotone over grid here
        }
        g_cut[i] = cut;
    }
    __syncthreads();
    for (int i = tid; i < HH * DD; i += 512) {
        int d = i & 63, h = i >> 6;
        float c = 0.0f;
        for (int q = 0; q < h; q++) c += g_mu[q * 64 + d];
        float s0 = x[(LL - 1) * 64 + d];
        g_base[i] = ((h == 0) ? s0 : (s0 + c)) + g_a20[i];
    }
    if (tid == 0) {
        unsigned seed = (unsigned)(*seed_ptr);
        uint2 key = make_uint2(0u, seed);
        g_kdiff = tf2x32(key.x, key.y, 0u, 0u);
        uint2 kp = tf2x32(key.x, key.y, 0u, 1u);
        g_kjmag = tf2x32(key.x, key.y, 0u, 2u);
        uint2 rng = kp;
        for (int t = 1; t <= NSUB; t++) {
            uint2 nr = tf2x32(rng.x, rng.y, 0u, 0u);
            g_sub[t] = tf2x32(rng.x, rng.y, 0u, 1u);
            rng = nr;
        }
    }
}

// ---------------- Kernel C: main Monte-Carlo (deferred rare work) ---------
__global__ void __launch_bounds__(256) mjd_main(float* __restrict__ out) {
    __shared__ unsigned sqe[8][QMAX];   // packed: e | (origin_lane << 25)
    __shared__ float    squ[8][QMAX];   // u1 at queue time
    __shared__ float    sjn[8][32];
    __shared__ float    swj[8][32];

    int tid = blockIdx.x * 256 + threadIdx.x;   // = (k*H + h)*D + d
    int lane = threadIdx.x & 31, wp = threadIdx.x >> 5;
    sjn[wp][lane] = 0.0f;
    swj[wp][lane] = 0.0f;

    int d  = tid & (DD - 1);
    int kh = tid >> 6;
    int hd = (kh % HH) * DD + d;

    float mlam = g_mlam[hd];
    float cut  = g_cut[hd];
    float nu = g_nu[hd], gm = g_gm[hd], ssd = g_ssd[hd], base = g_base[hd];
    uint2 kdiff = g_kdiff, kjmag = g_kjmag, sub1 = g_sub[1];

    unsigned e = (unsigned)kh * (MM * DD) + (unsigned)d;
    const unsigned lmask = (1u << lane) - 1u;

    float accd = 0.0f, jn_loc = 0.0f, wj_loc = 0.0f;
    int cnt = 0;

    // -------- phase 1: unconditional work, queue rare continuations --------
    #pragma unroll 2
    for (int m = 0; m < MM; m++) {
        // diffusion normal (always)
        accd += jnorm_fast(tf_bits(kdiff, e));

        // poisson first draw: threshold compare == (logf(u) > mlam) exactly
        float u = u01(tf_bits(sub1, e));
        bool need = u > cut;                 // nj >= 1
        unsigned bm = __ballot_sync(0xffffffffu, need);
        if (bm) {
            int add = __popc(bm);
            if (cnt + add <= QMAX) {
                if (need) {
                    int pos = cnt + __popc(bm & lmask);
                    sqe[wp][pos] = e | ((unsigned)lane << 25);
                    squ[wp][pos] = u;
                }
                cnt += add;
            } else if (need) {
                // overflow fallback: resolve inline with precise logf
                float lp = logf(u);
                float njf = 0.0f;
                int t = 2;
                do {
                    lp += logf(u01(tf_bits(g_sub[t], e)));
                    t++; njf += 1.0f;
                } while (lp > mlam && t <= NSUB);
                jn_loc += njf;
                wj_loc += sqrtf(njf) * jnorm_fast(tf_bits(kjmag, e));
            }
        }
        e += DD;
    }

    __syncwarp();

    // -------- phase 2: packed processing of queued items --------
    for (int bse = 0; bse < cnt; bse += 32) {
        int idx = bse + lane;
        bool act = idx < cnt;
        unsigned pk = act ? sqe[wp][idx] : 0u;
        float uq    = act ? squ[wp][idx] : 0.5f;
        unsigned ee = pk & 0x01FFFFFFu;
        int org     = (int)(pk >> 25);
        float mlam_o = __shfl_sync(0xffffffffu, mlam, org);
        if (act) {
            float lp = logf(uq);            // precise: decisions must match
            float njf = 0.0f;
            int t = 2;
            do {
                lp += logf(u01(tf_bits(g_sub[t], ee)));
                t++; njf += 1.0f;
            } while (lp > mlam_o && t <= NSUB);
            float ej = jnorm_fast(tf_bits(kjmag, ee));
            atomicAdd(&sjn[wp][org], njf);
            atomicAdd(&swj[wp][org], sqrtf(njf) * ej);
        }
    }

    __syncwarp();

    float jn = jn_loc + sjn[wp][lane];
    float wj = wj_loc + swj[wp][lane];
    out[tid] = (base + ssd * accd) + (nu * jn + gm * wj);
}

// ---------------- launch ----------------
extern "C" void kernel_launch(void* const* d_in, const int* in_sizes, int n_in,
                              void* d_out, int out_size) {
    const float* x  = (const float*)d_in[0];
    const float* W0 = (const float*)d_in[1];
    const float* b0 = (const float*)d_in[2];
    const float* W1 = (const float*)d_in[3];
    const float* b1 = (const float*)d_in[4];
    const float* W2 = (const float*)d_in[5];
    const float* b2 = (const float*)d_in[6];
    const float* W3 = (const float*)d_in[7];
    const float* b3 = (const float*)d_in[8];
    const int* seed = (const int*)d_in[11];
    float* out = (float*)d_out;

    float *bufA, *bufB, *raw;
    cudaGetSymbolAddress((void**)&bufA, g_bufA);
    cudaGetSymbolAddress((void**)&bufB, g_bufB);
    cudaGetSymbolAddress((void**)&raw,  g_raw);

    enc_layer<LL,  true ><<<WID,    256>>>(W0, b0, x,    bufA);
    enc_layer<WID, true ><<<WID,    256>>>(W1, b1, bufA, bufB);
    enc_layer<WID, true ><<<WID,    256>>>(W2, b2, bufB, bufA);
    enc_layer<WID, false><<<HH * 5, 256>>>(W3, b3, bufA, raw);
    finalize_kernel<<<1, 512>>>(x, seed);
    mjd_main<<<out_size / 256, 256>>>(out);
}

// round 6
// speedup vs baseline: 2.0877x; 1.0095x over previous
#include <cuda_runtime.h>
#include <cstdint>

// ---------------------------------------------------------------------------
// NeuralMJDFinancial: exact JAX (threefry-partitionable) reproduction.
// L=96, D=64, H=24, WID=256, K=1024, M=20. Output (K,H,D) f32.
//
// R6 vs R5 (258.5us, rel_err 2.7e-7):
//  * erfinv: rare (w>=5) arm gated behind warp vote (values identical)
//  * mjd phase 2: unconditional jnorm (safe full-mask vote), act-guarded atomics
//  * finalize: key chain depth 64 -> 24 (P(deeper) ~ 1e-24)
//  * encoder: full unroll (same accumulation order as R5 -> same decisions)
//  * mjd m-loop unroll 4
// ---------------------------------------------------------------------------

#define DD 64
#define HH 24
#define LL 96
#define WID 256
#define MM 20
#define NSUB 24
#define QMAX 128

__device__ float g_bufA[WID * DD];
__device__ float g_bufB[WID * DD];
__device__ float g_raw[HH * 5 * DD];
__device__ float g_mu[HH * DD];
__device__ float g_base[HH * DD];
__device__ float g_ssd[HH * DD];
__device__ float g_mlam[HH * DD];
__device__ float g_cut[HH * DD];
__device__ float g_nu[HH * DD];
__device__ float g_gm[HH * DD];
__device__ float g_a20[HH * DD];
__device__ uint2 g_kdiff;
__device__ uint2 g_kjmag;
__device__ uint2 g_sub[NSUB + 2];

// ---------------- Threefry-2x32, 20 rounds ----------------
#define TFR(r) { x0 += x1; x1 = __funnelshift_l(x1, x1, (r)); x1 ^= x0; }

__device__ __forceinline__ uint2 tf2x32(unsigned k0, unsigned k1,
                                        unsigned x0, unsigned x1) {
    unsigned k2 = k0 ^ k1 ^ 0x1BD11BDAu;
    x0 += k0; x1 += k1;
    TFR(13) TFR(15) TFR(26) TFR(6)
    x0 += k1; x1 += k2 + 1u;
    TFR(17) TFR(29) TFR(16) TFR(24)
    x0 += k2; x1 += k0 + 2u;
    TFR(13) TFR(15) TFR(26) TFR(6)
    x0 += k0; x1 += k1 + 3u;
    TFR(17) TFR(29) TFR(16) TFR(24)
    x0 += k1; x1 += k2 + 4u;
    TFR(13) TFR(15) TFR(26) TFR(6)
    x0 += k2; x1 += k0 + 5u;
    return make_uint2(x0, x1);
}

__device__ __forceinline__ unsigned tf_bits(uint2 key, unsigned e) {
    uint2 r = tf2x32(key.x, key.y, 0u, e);
    return r.x ^ r.y;
}

__device__ __forceinline__ float u01(unsigned b) {
    return __uint_as_float((b >> 9) | 0x3f800000u) - 1.0f;
}

__device__ __forceinline__ float erfinv_common(float w) {
    float ww = w - 2.5f;
    float p = 2.81022636e-08f;
    p = fmaf(p, ww, 3.43273939e-07f);
    p = fmaf(p, ww, -3.5233877e-06f);
    p = fmaf(p, ww, -4.39150654e-06f);
    p = fmaf(p, ww, 0.00021858087f);
    p = fmaf(p, ww, -0.00125372503f);
    p = fmaf(p, ww, -0.00417768164f);
    p = fmaf(p, ww, 0.246640727f);
    p = fmaf(p, ww, 1.50140941f);
    return p;
}

__device__ __forceinline__ float erfinv_rare(float w) {
    float wr = sqrtf(w) - 3.0f;
    float q = -0.000200214257f;
    q = fmaf(q, wr, 0.000100950558f);
    q = fmaf(q, wr, 0.00134934322f);
    q = fmaf(q, wr, -0.00367342844f);
    q = fmaf(q, wr, 0.00573950773f);
    q = fmaf(q, wr, -0.0076224613f);
    q = fmaf(q, wr, 0.00943887047f);
    q = fmaf(q, wr, 1.00167406f);
    q = fmaf(q, wr, 2.83297682f);
    return q;
}

// fast normal, warp-voted rare arm. REQUIRES all 32 lanes converged.
__device__ __forceinline__ float jnorm_fast(unsigned bits) {
    const float LO = -0.99999994f;  // 0xBF7FFFFF
    float f = u01(bits);
    float x = fmaxf(LO, fmaf(f, 2.0f, LO));
    float w = -__logf(fmaf(x, -x, 1.0f));
    float p = erfinv_common(w);
    if (__any_sync(0xffffffffu, w >= 5.0f)) {
        if (w >= 5.0f) p = erfinv_rare(w);
    }
    return 1.41421356237309515f * p * x;
}

// divergence-safe variant (no vote) for the cold overflow path
__device__ __forceinline__ float jnorm_safe(unsigned bits) {
    const float LO = -0.99999994f;
    float f = u01(bits);
    float x = fmaxf(LO, fmaf(f, 2.0f, LO));
    float w = -__logf(fmaf(x, -x, 1.0f));
    float p = (w < 5.0f) ? erfinv_common(w) : erfinv_rare(w);
    return 1.41421356237309515f * p * x;
}

__device__ __forceinline__ float jsigmoid(float x) {
    return 1.0f / (1.0f + expf(-x));
}

// ---------------- Encoder: one block per output row, all 64 channels ------
// Accumulation order identical to R5 (sequential j, then 4-way tree) so the
// Poisson thresholds downstream see bit-identical parameters.
template<int K, bool RELU>
__global__ void __launch_bounds__(256) enc_layer(
        const float* __restrict__ W, const float* __restrict__ b,
        const float* __restrict__ in, float* __restrict__ outp) {
    const int KS = K / 4;
    int tid = threadIdx.x;
    int d = tid & 63, ks = tid >> 6;
    int w = blockIdx.x;
    const float* Wr  = W + w * K + ks * KS;
    const float* inp = in + ks * KS * 64 + d;
    float acc = 0.0f;
    #pragma unroll
    for (int j = 0; j < KS; j++)
        acc = fmaf(Wr[j], inp[j * 64], acc);
    __shared__ float sp[256];
    sp[tid] = acc;
    __syncthreads();
    if (tid < 64) {
        float v = ((sp[tid] + sp[tid + 64]) + sp[tid + 128]) + sp[tid + 192];
        v += b[w];
        outp[w * 64 + tid] = RELU ? fmaxf(v, 0.0f) : v;
    }
}

// ---------------- finalize: params, cut thresholds, cumsum base, keys -----
__global__ void __launch_bounds__(512) finalize_kernel(
        const float* __restrict__ x, const int* __restrict__ seed_ptr) {
    int tid = threadIdx.x;
    for (int i = tid; i < HH * DD; i += 512) {
        int d = i & 63, h = i >> 6;
        float mu  = g_raw[(h * 5 + 0) * 64 + d];
        float sg  = jsigmoid(g_raw[(h * 5 + 1) * 64 + d]);
        float ll  = g_raw[(h * 5 + 2) * 64 + d];
        float nuv = tanhf(g_raw[(h * 5 + 3) * 64 + d]) * 0.5f;
        float gmv = jsigmoid(g_raw[(h * 5 + 4) * 64 + d]);
        float lam = expf(fminf(ll, 0.0f));
        float km  = expf(nuv + 0.5f * gmv * gmv) - 1.0f;
        float alpha = (mu - lam * km - 0.5f * sg * sg) * 0.05f;
        g_mu[i]  = mu;
        g_ssd[i] = sg * sqrtf(0.05f);
        g_nu[i]  = nuv;
        g_gm[i]  = gmv;
        g_a20[i] = 20.0f * alpha;
        float mlam = -(lam / 20.0f);
        g_mlam[i] = mlam;
        // exact cut: largest grid u with logf(u) <= mlam (u-grid = j*2^-23),
        // reproducing (logf(u) > mlam) decisions bit-identically.
        float t = expf(mlam);
        int j0 = (int)(t * 8388608.0f);
        int lo = j0 - 8 < 0 ? 0 : j0 - 8;
        int hi = j0 + 8 > 8388607 ? 8388607 : j0 + 8;
        float cut = 0.0f;
        for (int j = lo; j <= hi; j++) {
            float u = __uint_as_float(0x3f800000u | (unsigned)j) - 1.0f;
            if (logf(u) <= mlam) cut = u;
        }
        g_cut[i] = cut;
    }
    __syncthreads();
    for (int i = tid; i < HH * DD; i += 512) {
        int d = i & 63, h = i >> 6;
        float c = 0.0f;
        for (int q = 0; q < h; q++) c += g_mu[q * 64 + d];
        float s0 = x[(LL - 1) * 64 + d];
        g_base[i] = ((h == 0) ? s0 : (s0 + c)) + g_a20[i];
    }
    if (tid == 0) {
        unsigned seed = (unsigned)(*seed_ptr);
        uint2 key = make_uint2(0u, seed);
        g_kdiff = tf2x32(key.x, key.y, 0u, 0u);
        uint2 kp = tf2x32(key.x, key.y, 0u, 1u);
        g_kjmag = tf2x32(key.x, key.y, 0u, 2u);
        uint2 rng = kp;
        for (int t = 1; t <= NSUB; t++) {
            uint2 nr = tf2x32(rng.x, rng.y, 0u, 0u);
            g_sub[t] = tf2x32(rng.x, rng.y, 0u, 1u);
            rng = nr;
        }
    }
}

// ---------------- Kernel C: main Monte-Carlo (deferred rare work) ---------
__global__ void __launch_bounds__(256) mjd_main(float* __restrict__ out) {
    __shared__ unsigned sqe[8][QMAX];   // packed: e | (origin_lane << 25)
    __shared__ float    squ[8][QMAX];   // u1 at queue time
    __shared__ float    sjn[8][32];
    __shared__ float    swj[8][32];

    int tid = blockIdx.x * 256 + threadIdx.x;   // = (k*H + h)*D + d
    int lane = threadIdx.x & 31, wp = threadIdx.x >> 5;
    sjn[wp][lane] = 0.0f;
    swj[wp][lane] = 0.0f;

    int d  = tid & (DD - 1);
    int kh = tid >> 6;
    int hd = (kh % HH) * DD + d;

    float mlam = g_mlam[hd];
    float cut  = g_cut[hd];
    float nu = g_nu[hd], gm = g_gm[hd], ssd = g_ssd[hd], base = g_base[hd];
    uint2 kdiff = g_kdiff, kjmag = g_kjmag, sub1 = g_sub[1];

    unsigned e = (unsigned)kh * (MM * DD) + (unsigned)d;
    const unsigned lmask = (1u << lane) - 1u;

    float accd = 0.0f, jn_loc = 0.0f, wj_loc = 0.0f;
    int cnt = 0;

    // -------- phase 1: unconditional work, queue rare continuations --------
    #pragma unroll 4
    for (int m = 0; m < MM; m++) {
        // diffusion normal (always)
        accd += jnorm_fast(tf_bits(kdiff, e));

        // poisson first draw: threshold compare == (logf(u) > mlam) exactly
        float u = u01(tf_bits(sub1, e));
        bool need = u > cut;                 // nj >= 1
        unsigned bm = __ballot_sync(0xffffffffu, need);
        if (bm) {
            int add = __popc(bm);
            if (cnt + add <= QMAX) {
                if (need) {
                    int pos = cnt + __popc(bm & lmask);
                    sqe[wp][pos] = e | ((unsigned)lane << 25);
                    squ[wp][pos] = u;
                }
                cnt += add;
            } else if (need) {
                // cold overflow fallback (never taken at these rates)
                float lp = logf(u);
                float njf = 0.0f;
                int t = 2;
                do {
                    lp += logf(u01(tf_bits(g_sub[t], e)));
                    t++; njf += 1.0f;
                } while (lp > mlam && t <= NSUB);
                jn_loc += njf;
                wj_loc += sqrtf(njf) * jnorm_safe(tf_bits(kjmag, e));
            }
        }
        e += DD;
    }

    __syncwarp();

    // -------- phase 2: packed processing (fully convergent warp) --------
    for (int bse = 0; bse < cnt; bse += 32) {
        int idx = bse + lane;
        bool act = idx < cnt;
        unsigned pk = act ? sqe[wp][idx] : 0u;
        float uq    = act ? squ[wp][idx] : 0.0f;   // logf(0)=-inf -> exits fast
        unsigned ee = pk & 0x01FFFFFFu;
        int org     = (int)(pk >> 25);
        float mlam_o = __shfl_sync(0xffffffffu, mlam, org);

        float lp = logf(uq);                 // precise: decisions must match
        float njf = 0.0f;
        int t = 2;
        do {
            lp += logf(u01(tf_bits(g_sub[t], ee)));
            t++; njf += 1.0f;
        } while (lp > mlam_o && t <= NSUB);
        float ej = jnorm_fast(tf_bits(kjmag, ee));
        if (act) {
            atomicAdd(&sjn[wp][org], njf);
            atomicAdd(&swj[wp][org], sqrtf(njf) * ej);
        }
    }

    __syncwarp();

    float jn = jn_loc + sjn[wp][lane];
    float wj = wj_loc + swj[wp][lane];
    out[tid] = (base + ssd * accd) + (nu * jn + gm * wj);
}

// ---------------- launch ----------------
extern "C" void kernel_launch(void* const* d_in, const int* in_sizes, int n_in,
                              void* d_out, int out_size) {
    const float* x  = (const float*)d_in[0];
    const float* W0 = (const float*)d_in[1];
    const float* b0 = (const float*)d_in[2];
    const float* W1 = (const float*)d_in[3];
    const float* b1 = (const float*)d_in[4];
    const float* W2 = (const float*)d_in[5];
    const float* b2 = (const float*)d_in[6];
    const float* W3 = (const float*)d_in[7];
    const float* b3 = (const float*)d_in[8];
    const int* seed = (const int*)d_in[11];
    float* out = (float*)d_out;

    float *bufA, *bufB, *raw;
    cudaGetSymbolAddress((void**)&bufA, g_bufA);
    cudaGetSymbolAddress((void**)&bufB, g_bufB);
    cudaGetSymbolAddress((void**)&raw,  g_raw);

    enc_layer<LL,  true ><<<WID,    256>>>(W0, b0, x,    bufA);
    enc_layer<WID, true ><<<WID,    256>>>(W1, b1, bufA, bufB);
    enc_layer<WID, true ><<<WID,    256>>>(W2, b2, bufB, bufA);
    enc_layer<WID, false><<<HH * 5, 256>>>(W3, b3, bufA, raw);
    finalize_kernel<<<1, 512>>>(x, seed);
    mjd_main<<<out_size / 256, 256>>>(out);
}

// round 7
// speedup vs baseline: 2.1716x; 1.0402x over previous
#include <cuda_runtime.h>
#include <cstdint>

// ---------------------------------------------------------------------------
// NeuralMJDFinancial: exact JAX (threefry-partitionable) reproduction.
// L=96, D=64, H=24, WID=256, K=1024, M=20. Output (K,H,D) f32.
//
// R7 vs R6 (256.1us, rel_err 2.728e-7):
//  * encoder 4 layers + finalize fused into ONE persistent kernel
//    (128 blocks, software grid barrier; per-row math instruction-identical
//    to R6 so all Poisson decisions stay bit-identical; key chain overlapped)
//  * mjd phase 1: integer threshold compare + per-lane bitmask; queue built
//    once post-loop via shfl prefix sum; phase 2 recomputes u1 (same bits)
// ---------------------------------------------------------------------------

#define DD 64
#define HH 24
#define LL 96
#define WID 256
#define MM 20
#define NSUB 24
#define QMAX 192
#define NBLK 128

__device__ float g_bufA[WID * DD];
__device__ float g_bufB[WID * DD];
__device__ float g_bufC[WID * DD];
__device__ float g_raw[HH * 5 * DD];
__device__ float g_mu[HH * DD];
__device__ float g_base[HH * DD];
__device__ float g_ssd[HH * DD];
__device__ float g_mlam[HH * DD];
__device__ unsigned g_jcut[HH * DD];   // integer decision threshold on (bits>>9)
__device__ float g_nu[HH * DD];
__device__ float g_gm[HH * DD];
__device__ float g_a20[HH * DD];
__device__ uint2 g_kdiff;
__device__ uint2 g_kjmag;
__device__ uint2 g_sub[NSUB + 2];
__device__ unsigned g_bar_cnt;   // zero-init; self-resets each barrier
__device__ unsigned g_bar_gen;   // monotone across launches (harmless)

// ---------------- Threefry-2x32, 20 rounds ----------------
#define TFR(r) { x0 += x1; x1 = __funnelshift_l(x1, x1, (r)); x1 ^= x0; }

__device__ __forceinline__ uint2 tf2x32(unsigned k0, unsigned k1,
                                        unsigned x0, unsigned x1) {
    unsigned k2 = k0 ^ k1 ^ 0x1BD11BDAu;
    x0 += k0; x1 += k1;
    TFR(13) TFR(15) TFR(26) TFR(6)
    x0 += k1; x1 += k2 + 1u;
    TFR(17) TFR(29) TFR(16) TFR(24)
    x0 += k2; x1 += k0 + 2u;
    TFR(13) TFR(15) TFR(26) TFR(6)
    x0 += k0; x1 += k1 + 3u;
    TFR(17) TFR(29) TFR(16) TFR(24)
    x0 += k1; x1 += k2 + 4u;
    TFR(13) TFR(15) TFR(26) TFR(6)
    x0 += k2; x1 += k0 + 5u;
    return make_uint2(x0, x1);
}

__device__ __forceinline__ unsigned tf_bits(uint2 key, unsigned e) {
    uint2 r = tf2x32(key.x, key.y, 0u, e);
    return r.x ^ r.y;
}

__device__ __forceinline__ float u01(unsigned b) {
    return __uint_as_float((b >> 9) | 0x3f800000u) - 1.0f;
}

__device__ __forceinline__ float erfinv_common(float w) {
    float ww = w - 2.5f;
    float p = 2.81022636e-08f;
    p = fmaf(p, ww, 3.43273939e-07f);
    p = fmaf(p, ww, -3.5233877e-06f);
    p = fmaf(p, ww, -4.39150654e-06f);
    p = fmaf(p, ww, 0.00021858087f);
    p = fmaf(p, ww, -0.00125372503f);
    p = fmaf(p, ww, -0.00417768164f);
    p = fmaf(p, ww, 0.246640727f);
    p = fmaf(p, ww, 1.50140941f);
    return p;
}

__device__ __forceinline__ float erfinv_rare(float w) {
    float wr = sqrtf(w) - 3.0f;
    float q = -0.000200214257f;
    q = fmaf(q, wr, 0.000100950558f);
    q = fmaf(q, wr, 0.00134934322f);
    q = fmaf(q, wr, -0.00367342844f);
    q = fmaf(q, wr, 0.00573950773f);
    q = fmaf(q, wr, -0.0076224613f);
    q = fmaf(q, wr, 0.00943887047f);
    q = fmaf(q, wr, 1.00167406f);
    q = fmaf(q, wr, 2.83297682f);
    return q;
}

// fast normal, warp-voted rare arm. REQUIRES all 32 lanes converged.
__device__ __forceinline__ float jnorm_fast(unsigned bits) {
    const float LO = -0.99999994f;  // 0xBF7FFFFF
    float f = u01(bits);
    float x = fmaxf(LO, fmaf(f, 2.0f, LO));
    float w = -__logf(fmaf(x, -x, 1.0f));
    float p = erfinv_common(w);
    if (__any_sync(0xffffffffu, w >= 5.0f)) {
        if (w >= 5.0f) p = erfinv_rare(w);
    }
    return 1.41421356237309515f * p * x;
}

// divergence-safe variant (no vote) for the cold overflow path
__device__ __forceinline__ float jnorm_safe(unsigned bits) {
    const float LO = -0.99999994f;
    float f = u01(bits);
    float x = fmaxf(LO, fmaf(f, 2.0f, LO));
    float w = -__logf(fmaf(x, -x, 1.0f));
    float p = (w < 5.0f) ? erfinv_common(w) : erfinv_rare(w);
    return 1.41421356237309515f * p * x;
}

__device__ __forceinline__ float jsigmoid(float x) {
    return 1.0f / (1.0f + expf(-x));
}

// ---------------- software grid barrier (all NBLK blocks resident) --------
__device__ __forceinline__ void gridbar() {
    __syncthreads();
    if (threadIdx.x == 0) {
        __threadfence();
        unsigned gen = *(volatile unsigned*)&g_bar_gen;
        if (atomicAdd(&g_bar_cnt, 1u) == NBLK - 1u) {
            g_bar_cnt = 0u;
            __threadfence();
            atomicAdd(&g_bar_gen, 1u);
        } else {
            while (*(volatile unsigned*)&g_bar_gen == gen) { }
        }
        __threadfence();
    }
    __syncthreads();
}

// one output row of a layer; math identical to R6's enc_layer body
template<int K, bool RELU>
__device__ __forceinline__ void enc_row(
        const float* __restrict__ W, const float* __restrict__ b,
        const float* __restrict__ in, float* __restrict__ outp,
        int w, float* sp, int tid) {
    const int KS = K / 4;
    int d = tid & 63, ks = tid >> 6;
    const float* Wr  = W + w * K + ks * KS;
    const float* inp = in + ks * KS * 64 + d;
    float acc = 0.0f;
    #pragma unroll
    for (int j = 0; j < KS; j++)
        acc = fmaf(Wr[j], inp[j * 64], acc);
    sp[tid] = acc;
    __syncthreads();
    if (tid < 64) {
        float v = ((sp[tid] + sp[tid + 64]) + sp[tid + 128]) + sp[tid + 192];
        v += b[w];
        outp[w * 64 + tid] = RELU ? fmaxf(v, 0.0f) : v;
    }
    __syncthreads();
}

// ---------------- persistent encoder + finalize ----------------
__global__ void __launch_bounds__(256) enc_persist(
        const float* __restrict__ x,
        const float* __restrict__ W0, const float* __restrict__ b0,
        const float* __restrict__ W1, const float* __restrict__ b1,
        const float* __restrict__ W2, const float* __restrict__ b2,
        const float* __restrict__ W3, const float* __restrict__ b3,
        const int* __restrict__ seed_ptr) {
    __shared__ float sp[256];
    int tid = threadIdx.x, bid = blockIdx.x;

    // RNG key chain: runs on block 127 concurrently with layer 0
    if (bid == NBLK - 1 && tid == 0) {
        unsigned seed = (unsigned)(*seed_ptr);
        uint2 key = make_uint2(0u, seed);
        g_kdiff = tf2x32(key.x, key.y, 0u, 0u);
        uint2 kp = tf2x32(key.x, key.y, 0u, 1u);
        g_kjmag = tf2x32(key.x, key.y, 0u, 2u);
        uint2 rng = kp;
        for (int t = 1; t <= NSUB; t++) {
            uint2 nr = tf2x32(rng.x, rng.y, 0u, 0u);
            g_sub[t] = tf2x32(rng.x, rng.y, 0u, 1u);
            rng = nr;
        }
        __threadfence();
    }

    enc_row<LL,  true>(W0, b0, x,      g_bufA, 2 * bid,     sp, tid);
    enc_row<LL,  true>(W0, b0, x,      g_bufA, 2 * bid + 1, sp, tid);
    gridbar();
    enc_row<WID, true>(W1, b1, g_bufA, g_bufB, 2 * bid,     sp, tid);
    enc_row<WID, true>(W1, b1, g_bufA, g_bufB, 2 * bid + 1, sp, tid);
    gridbar();
    enc_row<WID, true>(W2, b2, g_bufB, g_bufC, 2 * bid,     sp, tid);
    enc_row<WID, true>(W2, b2, g_bufB, g_bufC, 2 * bid + 1, sp, tid);
    gridbar();
    if (bid < HH * 5)
        enc_row<WID, false>(W3, b3, g_bufC, g_raw, bid, sp, tid);
    gridbar();

    // params + integer cut thresholds (one item per thread)
    int g = bid * 256 + tid;
    if (g < HH * DD) {
        int i = g;
        int d = i & 63, h = i >> 6;
        float mu  = g_raw[(h * 5 + 0) * 64 + d];
        float sg  = jsigmoid(g_raw[(h * 5 + 1) * 64 + d]);
        float ll  = g_raw[(h * 5 + 2) * 64 + d];
        float nuv = tanhf(g_raw[(h * 5 + 3) * 64 + d]) * 0.5f;
        float gmv = jsigmoid(g_raw[(h * 5 + 4) * 64 + d]);
        float lam = expf(fminf(ll, 0.0f));
        float km  = expf(nuv + 0.5f * gmv * gmv) - 1.0f;
        float alpha = (mu - lam * km - 0.5f * sg * sg) * 0.05f;
        g_mu[i]  = mu;
        g_ssd[i] = sg * sqrtf(0.05f);
        g_nu[i]  = nuv;
        g_gm[i]  = gmv;
        g_a20[i] = 20.0f * alpha;
        float mlam = -(lam / 20.0f);
        g_mlam[i] = mlam;
        // largest grid index j with logf(u_j) <= mlam; decision (logf(u)>mlam)
        // becomes (bits>>9) > jcut, bit-identically (u-grid monotone in j)
        float t = expf(mlam);
        int j0 = (int)(t * 8388608.0f);
        int lo = j0 - 8 < 0 ? 0 : j0 - 8;
        int hi = j0 + 8 > 8388607 ? 8388607 : j0 + 8;
        unsigned jc = 0u;
        for (int j = lo; j <= hi; j++) {
            float u = __uint_as_float(0x3f800000u | (unsigned)j) - 1.0f;
            if (logf(u) <= mlam) jc = (unsigned)j;
        }
        g_jcut[i] = jc;
    }
    gridbar();

    // cumsum base (same per-item arithmetic as R6 finalize)
    if (g < HH * DD) {
        int i = g;
        int d = i & 63, h = i >> 6;
        float c = 0.0f;
        for (int q = 0; q < h; q++) c += g_mu[q * 64 + d];
        float s0 = x[(LL - 1) * 64 + d];
        g_base[i] = ((h == 0) ? s0 : (s0 + c)) + g_a20[i];
    }
}

// ---------------- Kernel C: main Monte-Carlo (deferred rare work) ---------
__global__ void __launch_bounds__(256) mjd_main(float* __restrict__ out) {
    __shared__ unsigned sq[8][QMAX];    // packed: m | (origin_lane << 8)
    __shared__ float    sjn[8][32];
    __shared__ float    swj[8][32];

    int tid = blockIdx.x * 256 + threadIdx.x;   // = (k*H + h)*D + d
    int lane = threadIdx.x & 31, wp = threadIdx.x >> 5;
    sjn[wp][lane] = 0.0f;
    swj[wp][lane] = 0.0f;

    int d  = tid & (DD - 1);
    int kh = tid >> 6;                 // uniform within a warp
    int hd = (kh % HH) * DD + d;

    float mlam = g_mlam[hd];
    unsigned jcut = g_jcut[hd];
    float nu = g_nu[hd], gm = g_gm[hd], ssd = g_ssd[hd], base = g_base[hd];
    uint2 kdiff = g_kdiff, kjmag = g_kjmag, sub1 = g_sub[1];

    const unsigned e0 = (unsigned)kh * (MM * DD) + (unsigned)d;
    unsigned e = e0;

    float accd = 0.0f, jn_loc = 0.0f, wj_loc = 0.0f;
    unsigned pmask = 0u;

    // -------- phase 1: unconditional work only; mark rare continuations ----
    #pragma unroll 4
    for (int m = 0; m < MM; m++) {
        accd += jnorm_fast(tf_bits(kdiff, e));
        unsigned b = tf_bits(sub1, e);
        if ((b >> 9) > jcut) pmask |= (1u << m);   // == (logf(u) > mlam)
        e += DD;
    }

    // -------- compact events into per-warp queue (shfl prefix sum) --------
    int c = __popc(pmask);
    int off = c;
    #pragma unroll
    for (int o = 1; o < 32; o <<= 1) {
        int v = __shfl_up_sync(0xffffffffu, off, o);
        if (lane >= o) off += v;
    }
    int pos = off - c;                       // exclusive prefix
    int total = __shfl_sync(0xffffffffu, off, 31);
    unsigned pm = pmask;
    while (pm) {
        int m = __ffs(pm) - 1;
        pm &= pm - 1u;
        if (pos < QMAX) {
            sq[wp][pos] = (unsigned)m | ((unsigned)lane << 8);
        } else {
            // cold overflow fallback (effectively never at these rates)
            unsigned ee2 = e0 + (unsigned)(m * DD);
            float lp = logf(u01(tf_bits(sub1, ee2)));
            float njf = 0.0f;
            int t = 2;
            do {
                lp += logf(u01(tf_bits(g_sub[t], ee2)));
                t++; njf += 1.0f;
            } while (lp > mlam && t <= NSUB);
            jn_loc += njf;
            wj_loc += sqrtf(njf) * jnorm_safe(tf_bits(kjmag, ee2));
        }
        pos++;
    }
    if (total > QMAX) total = QMAX;
    __syncwarp();

    // -------- phase 2: packed processing (fully convergent warp) --------
    unsigned ewb = e0 - (unsigned)lane;      // warp-uniform base
    for (int bse = 0; bse < total; bse += 32) {
        int idx = bse + lane;
        bool act = idx < total;
        unsigned pk = act ? sq[wp][idx] : 0u;
        int m   = (int)(pk & 0xffu);
        int org = (int)(pk >> 8);
        unsigned ee = ewb + (unsigned)org + (unsigned)(m * DD);
        float mlam_o = __shfl_sync(0xffffffffu, mlam, org);

        float lp = logf(u01(tf_bits(sub1, ee)));   // same bits as phase 1
        float njf = 0.0f;
        int t = 2;
        do {
            lp += logf(u01(tf_bits(g_sub[t], ee)));
            t++; njf += 1.0f;
        } while (lp > mlam_o && t <= NSUB);
        float ej = jnorm_fast(tf_bits(kjmag, ee));
        if (act) {
            atomicAdd(&sjn[wp][org], njf);
            atomicAdd(&swj[wp][org], sqrtf(njf) * ej);
        }
    }

    __syncwarp();

    float jn = jn_loc + sjn[wp][lane];
    float wj = wj_loc + swj[wp][lane];
    out[tid] = (base + ssd * accd) + (nu * jn + gm * wj);
}

// ---------------- launch ----------------
extern "C" void kernel_launch(void* const* d_in, const int* in_sizes, int n_in,
                              void* d_out, int out_size) {
    const float* x  = (const float*)d_in[0];
    const float* W0 = (const float*)d_in[1];
    const float* b0 = (const float*)d_in[2];
    const float* W1 = (const float*)d_in[3];
    const float* b1 = (const float*)d_in[4];
    const float* W2 = (const float*)d_in[5];
    const float* b2 = (const float*)d_in[6];
    const float* W3 = (const float*)d_in[7];
    const float* b3 = (const float*)d_in[8];
    const int* seed = (const int*)d_in[11];
    float* out = (float*)d_out;

    enc_persist<<<NBLK, 256>>>(x, W0, b0, W1, b1, W2, b2, W3, b3, seed);
    mjd_main<<<out_size / 256, 256>>>(out);
}

// round 8
// speedup vs baseline: 2.2698x; 1.0452x over previous
#include <cuda_runtime.h>
#include <cstdint>

// ---------------------------------------------------------------------------
// NeuralMJDFinancial: exact JAX (threefry-partitionable) reproduction.
// L=96, D=64, H=24, WID=256, K=1024, M=20. Output (K,H,D) f32.
//
// R8 vs R7 (246.2us, rel_err 2.728e-7; mjd_main alu=86.9% fma=27.2% issue=78.1%):
//  * threefry round adds + x0 key injections forced to IMAD (fma pipe) via
//    mad.lo.u32 with opaque multiplier g_one -- rebalances alu<->fma pipes
//  * k2 hoisted out of hot threefry (loop-invariant keys)
//  * Poisson decision: b > bcut (== (b>>9) > jcut bit-identically; saves SHF)
// ---------------------------------------------------------------------------

#define DD 64
#define HH 24
#define LL 96
#define WID 256
#define MM 20
#define NSUB 24
#define QMAX 192
#define NBLK 128

__device__ float g_bufA[WID * DD];
__device__ float g_bufB[WID * DD];
__device__ float g_bufC[WID * DD];
__device__ float g_raw[HH * 5 * DD];
__device__ float g_mu[HH * DD];
__device__ float g_base[HH * DD];
__device__ float g_ssd[HH * DD];
__device__ float g_mlam[HH * DD];
__device__ unsigned g_bcut[HH * DD];   // decision: bits > bcut
__device__ float g_nu[HH * DD];
__device__ float g_gm[HH * DD];
__device__ float g_a20[HH * DD];
__device__ uint2 g_kdiff;
__device__ uint2 g_kjmag;
__device__ uint2 g_sub[NSUB + 2];
__device__ unsigned g_bar_cnt;
__device__ unsigned g_bar_gen;
__device__ unsigned g_one = 1u;   // opaque 1: forces IMAD (fma pipe)

// integer mad on the fma pipe (ptxas cannot fold: multiplier is opaque)
__device__ __forceinline__ unsigned imad(unsigned a, unsigned b, unsigned c) {
    unsigned r;
    asm("mad.lo.u32 %0, %1, %2, %3;" : "=r"(r) : "r"(a), "r"(b), "r"(c));
    return r;
}

// ---------------- Threefry-2x32, 20 rounds ----------------
// hot variant: round add + x0 injections on fma pipe, k2 precomputed
#define TFRI(r) { x0 = imad(x1, one, x0); x1 = __funnelshift_l(x1, x1, (r)); x1 ^= x0; }

__device__ __forceinline__ uint2 tf2x32_pre(unsigned k0, unsigned k1, unsigned k2,
                                            unsigned x0, unsigned x1, unsigned one) {
    x0 = imad(k0, one, x0); x1 += k1;
    TFRI(13) TFRI(15) TFRI(26) TFRI(6)
    x0 = imad(k1, one, x0); x1 += k2 + 1u;
    TFRI(17) TFRI(29) TFRI(16) TFRI(24)
    x0 = imad(k2, one, x0); x1 += k0 + 2u;
    TFRI(13) TFRI(15) TFRI(26) TFRI(6)
    x0 = imad(k0, one, x0); x1 += k1 + 3u;
    TFRI(17) TFRI(29) TFRI(16) TFRI(24)
    x0 = imad(k1, one, x0); x1 += k2 + 4u;
    TFRI(13) TFRI(15) TFRI(26) TFRI(6)
    x0 = imad(k2, one, x0); x1 += k0 + 5u;
    return make_uint2(x0, x1);
}

__device__ __forceinline__ unsigned tf_bits_pre(unsigned k0, unsigned k1, unsigned k2,
                                                unsigned e, unsigned one) {
    uint2 r = tf2x32_pre(k0, k1, k2, 0u, e, one);
    return r.x ^ r.y;
}

// cold/setup variant (plain, self-contained)
#define TFR(r) { x0 += x1; x1 = __funnelshift_l(x1, x1, (r)); x1 ^= x0; }

__device__ __forceinline__ uint2 tf2x32(unsigned k0, unsigned k1,
                                        unsigned x0, unsigned x1) {
    unsigned k2 = k0 ^ k1 ^ 0x1BD11BDAu;
    x0 += k0; x1 += k1;
    TFR(13) TFR(15) TFR(26) TFR(6)
    x0 += k1; x1 += k2 + 1u;
    TFR(17) TFR(29) TFR(16) TFR(24)
    x0 += k2; x1 += k0 + 2u;
    TFR(13) TFR(15) TFR(26) TFR(6)
    x0 += k0; x1 += k1 + 3u;
    TFR(17) TFR(29) TFR(16) TFR(24)
    x0 += k1; x1 += k2 + 4u;
    TFR(13) TFR(15) TFR(26) TFR(6)
    x0 += k2; x1 += k0 + 5u;
    return make_uint2(x0, x1);
}

__device__ __forceinline__ unsigned tf_bits(uint2 key, unsigned e) {
    uint2 r = tf2x32(key.x, key.y, 0u, e);
    return r.x ^ r.y;
}

__device__ __forceinline__ float u01(unsigned b) {
    return __uint_as_float((b >> 9) | 0x3f800000u) - 1.0f;
}

__device__ __forceinline__ float erfinv_common(float w) {
    float ww = w - 2.5f;
    float p = 2.81022636e-08f;
    p = fmaf(p, ww, 3.43273939e-07f);
    p = fmaf(p, ww, -3.5233877e-06f);
    p = fmaf(p, ww, -4.39150654e-06f);
    p = fmaf(p, ww, 0.00021858087f);
    p = fmaf(p, ww, -0.00125372503f);
    p = fmaf(p, ww, -0.00417768164f);
    p = fmaf(p, ww, 0.246640727f);
    p = fmaf(p, ww, 1.50140941f);
    return p;
}

__device__ __forceinline__ float erfinv_rare(float w) {
    float wr = sqrtf(w) - 3.0f;
    float q = -0.000200214257f;
    q = fmaf(q, wr, 0.000100950558f);
    q = fmaf(q, wr, 0.00134934322f);
    q = fmaf(q, wr, -0.00367342844f);
    q = fmaf(q, wr, 0.00573950773f);
    q = fmaf(q, wr, -0.0076224613f);
    q = fmaf(q, wr, 0.00943887047f);
    q = fmaf(q, wr, 1.00167406f);
    q = fmaf(q, wr, 2.83297682f);
    return q;
}

// fast normal, warp-voted rare arm. REQUIRES all 32 lanes converged.
__device__ __forceinline__ float jnorm_from_bits(unsigned bits) {
    const float LO = -0.99999994f;  // 0xBF7FFFFF
    float f = u01(bits);
    float x = fmaxf(LO, fmaf(f, 2.0f, LO));
    float w = -__logf(fmaf(x, -x, 1.0f));
    float p = erfinv_common(w);
    if (__any_sync(0xffffffffu, w >= 5.0f)) {
        if (w >= 5.0f) p = erfinv_rare(w);
    }
    return 1.41421356237309515f * p * x;
}

// divergence-safe variant (no vote) for the cold overflow path
__device__ __forceinline__ float jnorm_safe(unsigned bits) {
    const float LO = -0.99999994f;
    float f = u01(bits);
    float x = fmaxf(LO, fmaf(f, 2.0f, LO));
    float w = -__logf(fmaf(x, -x, 1.0f));
    float p = (w < 5.0f) ? erfinv_common(w) : erfinv_rare(w);
    return 1.41421356237309515f * p * x;
}

__device__ __forceinline__ float jsigmoid(float x) {
    return 1.0f / (1.0f + expf(-x));
}

// ---------------- software grid barrier (all NBLK blocks resident) --------
__device__ __forceinline__ void gridbar() {
    __syncthreads();
    if (threadIdx.x == 0) {
        __threadfence();
        unsigned gen = *(volatile unsigned*)&g_bar_gen;
        if (atomicAdd(&g_bar_cnt, 1u) == NBLK - 1u) {
            g_bar_cnt = 0u;
            __threadfence();
            atomicAdd(&g_bar_gen, 1u);
        } else {
            while (*(volatile unsigned*)&g_bar_gen == gen) { }
        }
        __threadfence();
    }
    __syncthreads();
}

// one output row of a layer; math identical to R6/R7
template<int K, bool RELU>
__device__ __forceinline__ void enc_row(
        const float* __restrict__ W, const float* __restrict__ b,
        const float* __restrict__ in, float* __restrict__ outp,
        int w, float* sp, int tid) {
    const int KS = K / 4;
    int d = tid & 63, ks = tid >> 6;
    const float* Wr  = W + w * K + ks * KS;
    const float* inp = in + ks * KS * 64 + d;
    float acc = 0.0f;
    #pragma unroll
    for (int j = 0; j < KS; j++)
        acc = fmaf(Wr[j], inp[j * 64], acc);
    sp[tid] = acc;
    __syncthreads();
    if (tid < 64) {
        float v = ((sp[tid] + sp[tid + 64]) + sp[tid + 128]) + sp[tid + 192];
        v += b[w];
        outp[w * 64 + tid] = RELU ? fmaxf(v, 0.0f) : v;
    }
    __syncthreads();
}

// ---------------- persistent encoder + finalize ----------------
__global__ void __launch_bounds__(256) enc_persist(
        const float* __restrict__ x,
        const float* __restrict__ W0, const float* __restrict__ b0,
        const float* __restrict__ W1, const float* __restrict__ b1,
        const float* __restrict__ W2, const float* __restrict__ b2,
        const float* __restrict__ W3, const float* __restrict__ b3,
        const int* __restrict__ seed_ptr) {
    __shared__ float sp[256];
    int tid = threadIdx.x, bid = blockIdx.x;

    // RNG key chain: block 127, concurrent with layer 0
    if (bid == NBLK - 1 && tid == 0) {
        unsigned seed = (unsigned)(*seed_ptr);
        uint2 key = make_uint2(0u, seed);
        g_kdiff = tf2x32(key.x, key.y, 0u, 0u);
        uint2 kp = tf2x32(key.x, key.y, 0u, 1u);
        g_kjmag = tf2x32(key.x, key.y, 0u, 2u);
        uint2 rng = kp;
        for (int t = 1; t <= NSUB; t++) {
            uint2 nr = tf2x32(rng.x, rng.y, 0u, 0u);
            g_sub[t] = tf2x32(rng.x, rng.y, 0u, 1u);
            rng = nr;
        }
        __threadfence();
    }

    enc_row<LL,  true>(W0, b0, x,      g_bufA, 2 * bid,     sp, tid);
    enc_row<LL,  true>(W0, b0, x,      g_bufA, 2 * bid + 1, sp, tid);
    gridbar();
    enc_row<WID, true>(W1, b1, g_bufA, g_bufB, 2 * bid,     sp, tid);
    enc_row<WID, true>(W1, b1, g_bufA, g_bufB, 2 * bid + 1, sp, tid);
    gridbar();
    enc_row<WID, true>(W2, b2, g_bufB, g_bufC, 2 * bid,     sp, tid);
    enc_row<WID, true>(W2, b2, g_bufB, g_bufC, 2 * bid + 1, sp, tid);
    gridbar();
    if (bid < HH * 5)
        enc_row<WID, false>(W3, b3, g_bufC, g_raw, bid, sp, tid);
    gridbar();

    // params + decision thresholds
    int g = bid * 256 + tid;
    if (g < HH * DD) {
        int i = g;
        int d = i & 63, h = i >> 6;
        float mu  = g_raw[(h * 5 + 0) * 64 + d];
        float sg  = jsigmoid(g_raw[(h * 5 + 1) * 64 + d]);
        float ll  = g_raw[(h * 5 + 2) * 64 + d];
        float nuv = tanhf(g_raw[(h * 5 + 3) * 64 + d]) * 0.5f;
        float gmv = jsigmoid(g_raw[(h * 5 + 4) * 64 + d]);
        float lam = expf(fminf(ll, 0.0f));
        float km  = expf(nuv + 0.5f * gmv * gmv) - 1.0f;
        float alpha = (mu - lam * km - 0.5f * sg * sg) * 0.05f;
        g_mu[i]  = mu;
        g_ssd[i] = sg * sqrtf(0.05f);
        g_nu[i]  = nuv;
        g_gm[i]  = gmv;
        g_a20[i] = 20.0f * alpha;
        float mlam = -(lam / 20.0f);
        g_mlam[i] = mlam;
        // largest grid index j with logf(u_j) <= mlam; the runtime decision
        // (logf(u) > mlam) == (bits > (j<<9 | 0x1FF)), bit-identically
        float t = expf(mlam);
        int j0 = (int)(t * 8388608.0f);
        int lo = j0 - 8 < 0 ? 0 : j0 - 8;
        int hi = j0 + 8 > 8388607 ? 8388607 : j0 + 8;
        unsigned jc = 0u;
        for (int j = lo; j <= hi; j++) {
            float u = __uint_as_float(0x3f800000u | (unsigned)j) - 1.0f;
            if (logf(u) <= mlam) jc = (unsigned)j;
        }
        g_bcut[i] = (jc << 9) | 0x1FFu;
    }
    gridbar();

    // cumsum base
    if (g < HH * DD) {
        int i = g;
        int d = i & 63, h = i >> 6;
        float c = 0.0f;
        for (int q = 0; q < h; q++) c += g_mu[q * 64 + d];
        float s0 = x[(LL - 1) * 64 + d];
        g_base[i] = ((h == 0) ? s0 : (s0 + c)) + g_a20[i];
    }
}

// ---------------- Kernel C: main Monte-Carlo (deferred rare work) ---------
__global__ void __launch_bounds__(256) mjd_main(float* __restrict__ out) {
    __shared__ unsigned sq[8][QMAX];    // packed: m | (origin_lane << 8)
    __shared__ float    sjn[8][32];
    __shared__ float    swj[8][32];

    int tid = blockIdx.x * 256 + threadIdx.x;   // = (k*H + h)*D + d
    int lane = threadIdx.x & 31, wp = threadIdx.x >> 5;
    sjn[wp][lane] = 0.0f;
    swj[wp][lane] = 0.0f;

    int d  = tid & (DD - 1);
    int kh = tid >> 6;                 // warp-uniform
    int hd = (kh % HH) * DD + d;

    float mlam = g_mlam[hd];
    unsigned bcut = g_bcut[hd];
    float nu = g_nu[hd], gm = g_gm[hd], ssd = g_ssd[hd], base = g_base[hd];
    uint2 kdiff = g_kdiff, kjmag = g_kjmag, sub1 = g_sub[1];
    const unsigned one = g_one;        // opaque 1 for IMAD forcing

    // hoisted key schedules
    const unsigned dk0 = kdiff.x, dk1 = kdiff.y, dk2 = dk0 ^ dk1 ^ 0x1BD11BDAu;
    const unsigned sk0 = sub1.x,  sk1 = sub1.y,  sk2 = sk0 ^ sk1 ^ 0x1BD11BDAu;
    const unsigned jk0 = kjmag.x, jk1 = kjmag.y, jk2 = jk0 ^ jk1 ^ 0x1BD11BDAu;

    const unsigned e0 = (unsigned)kh * (MM * DD) + (unsigned)d;
    unsigned e = e0;

    float accd = 0.0f, jn_loc = 0.0f, wj_loc = 0.0f;
    unsigned pmask = 0u;

    // -------- phase 1: unconditional work only; mark rare continuations ----
    #pragma unroll 4
    for (int m = 0; m < MM; m++) {
        accd += jnorm_from_bits(tf_bits_pre(dk0, dk1, dk2, e, one));
        unsigned b = tf_bits_pre(sk0, sk1, sk2, e, one);
        if (b > bcut) pmask |= (1u << m);   // == (logf(u) > mlam)
        e += DD;
    }

    // -------- compact events into per-warp queue (shfl prefix sum) --------
    int c = __popc(pmask);
    int off = c;
    #pragma unroll
    for (int o = 1; o < 32; o <<= 1) {
        int v = __shfl_up_sync(0xffffffffu, off, o);
        if (lane >= o) off += v;
    }
    int pos = off - c;                       // exclusive prefix
    int total = __shfl_sync(0xffffffffu, off, 31);
    unsigned pm = pmask;
    while (pm) {
        int m = __ffs(pm) - 1;
        pm &= pm - 1u;
        if (pos < QMAX) {
            sq[wp][pos] = (unsigned)m | ((unsigned)lane << 8);
        } else {
            // cold overflow fallback (effectively never at these rates)
            unsigned ee2 = e0 + (unsigned)(m * DD);
            float lp = logf(u01(tf_bits(sub1, ee2)));
            float njf = 0.0f;
            int t = 2;
            do {
                lp += logf(u01(tf_bits(g_sub[t], ee2)));
                t++; njf += 1.0f;
            } while (lp > mlam && t <= NSUB);
            jn_loc += njf;
            wj_loc += sqrtf(njf) * jnorm_safe(tf_bits(kjmag, ee2));
        }
        pos++;
    }
    if (total > QMAX) total = QMAX;
    __syncwarp();

    // -------- phase 2: packed processing (fully convergent warp) --------
    unsigned ewb = e0 - (unsigned)lane;      // warp-uniform base
    for (int bse = 0; bse < total; bse += 32) {
        int idx = bse + lane;
        bool act = idx < total;
        unsigned pk = act ? sq[wp][idx] : 0u;
        int m   = (int)(pk & 0xffu);
        int org = (int)(pk >> 8);
        unsigned ee = ewb + (unsigned)org + (unsigned)(m * DD);
        float mlam_o = __shfl_sync(0xffffffffu, mlam, org);

        float lp = logf(u01(tf_bits_pre(sk0, sk1, sk2, ee, one)));  // same bits
        float njf = 0.0f;
        int t = 2;
        do {
            lp += logf(u01(tf_bits(g_sub[t], ee)));
            t++; njf += 1.0f;
        } while (lp > mlam_o && t <= NSUB);
        float ej = jnorm_from_bits(tf_bits_pre(jk0, jk1, jk2, ee, one));
        if (act) {
            atomicAdd(&sjn[wp][org], njf);
            atomicAdd(&swj[wp][org], sqrtf(njf) * ej);
        }
    }

    __syncwarp();

    float jn = jn_loc + sjn[wp][lane];
    float wj = wj_loc + swj[wp][lane];
    out[tid] = (base + ssd * accd) + (nu * jn + gm * wj);
}

// ---------------- launch ----------------
extern "C" void kernel_launch(void* const* d_in, const int* in_sizes, int n_in,
                              void* d_out, int out_size) {
    const float* x  = (const float*)d_in[0];
    const float* W0 = (const float*)d_in[1];
    const float* b0 = (const float*)d_in[2];
    const float* W1 = (const float*)d_in[3];
    const float* b1 = (const float*)d_in[4];
    const float* W2 = (const float*)d_in[5];
    const float* b2 = (const float*)d_in[6];
    const float* W3 = (const float*)d_in[7];
    const float* b3 = (const float*)d_in[8];
    const int* seed = (const int*)d_in[11];
    float* out = (float*)d_out;

    enc_persist<<<NBLK, 256>>>(x, W0, b0, W1, b1, W2, b2, W3, b3, seed);
    mjd_main<<<out_size / 256, 256>>>(out);
}